// round 13
// baseline (speedup 1.0000x reference)
#include <cuda_runtime.h>
#include <cuda_bf16.h>
#include <math.h>
#include <stdint.h>

#define BATCH 64
#define NPG   2048
#define KMAX  64
#define DIN   256
#define DOUT  256
#define EDIM  16
#define NSEG  4
#define SEGN  (NPG/NSEG)

// Scratch (no allocations allowed)
__device__ float g_filt[BATCH*KMAX];                       // 16 KB
__device__ float g_part[(size_t)NSEG*BATCH*KMAX*DIN];      // 16 MB partial x_freq
// Z in mma-B-fragment order, h+l packed: [b][n8(32)][ks(4)][lane(32)] uint4
__device__ uint4 g_Zfrag[(size_t)BATCH*32*4*32];           // 4 MB

// ===========================================================================
// mma.sync helpers (portable tensor-core path; tcgen05 rejected by the
// harness's compute_103 virtual arch)
// ===========================================================================
__device__ __forceinline__ void ldmx4(uint32_t* r, uint32_t addr) {
    asm volatile("ldmatrix.sync.aligned.m8n8.x4.shared.b16 {%0,%1,%2,%3}, [%4];"
                 : "=r"(r[0]), "=r"(r[1]), "=r"(r[2]), "=r"(r[3]) : "r"(addr));
}
__device__ __forceinline__ void ldmx4t(uint32_t* r, uint32_t addr) {
    asm volatile("ldmatrix.sync.aligned.m8n8.x4.trans.shared.b16 {%0,%1,%2,%3}, [%4];"
                 : "=r"(r[0]), "=r"(r[1]), "=r"(r[2]), "=r"(r[3]) : "r"(addr));
}

__device__ __forceinline__ void mma_bf16(float* d, const uint32_t* a,
                                         uint32_t b0, uint32_t b1) {
    asm volatile(
        "mma.sync.aligned.m16n8k16.row.col.f32.bf16.bf16.f32 "
        "{%0,%1,%2,%3}, {%4,%5,%6,%7}, {%8,%9}, {%0,%1,%2,%3};"
        : "+f"(d[0]), "+f"(d[1]), "+f"(d[2]), "+f"(d[3])
        : "r"(a[0]), "r"(a[1]), "r"(a[2]), "r"(a[3]), "r"(b0), "r"(b1));
}

// Truncation-based hi/lo split: hi = top 16 bits (PRMT pack), lo = x - hi.
__device__ __forceinline__ void split_store(char* base_h, char* base_l,
                                            uint32_t off, float4 v) {
    uint32_t u0 = __float_as_uint(v.x), u1 = __float_as_uint(v.y);
    uint32_t u2 = __float_as_uint(v.z), u3 = __float_as_uint(v.w);
    uint32_t h01 = __byte_perm(u0, u1, 0x7632);
    uint32_t h23 = __byte_perm(u2, u3, 0x7632);
    float l0 = v.x + __uint_as_float((u0 & 0xFFFF0000u) ^ 0x80000000u);
    float l1 = v.y + __uint_as_float((u1 & 0xFFFF0000u) ^ 0x80000000u);
    float l2 = v.z + __uint_as_float((u2 & 0xFFFF0000u) ^ 0x80000000u);
    float l3 = v.w + __uint_as_float((u3 & 0xFFFF0000u) ^ 0x80000000u);
    uint32_t lo01 = __byte_perm(__float_as_uint(l0), __float_as_uint(l1), 0x7632);
    uint32_t lo23 = __byte_perm(__float_as_uint(l2), __float_as_uint(l3), 0x7632);
    *(uint2*)(base_h + off) = make_uint2(h01, h23);
    *(uint2*)(base_l + off) = make_uint2(lo01, lo23);
}

// ===========================================================================
// Kernel A: per-batch eigenvalue encoder + attention + filter MLP (tiny)
// ===========================================================================
__global__ void filter_kernel(
    const float* __restrict__ eigenvalues,
    const float* __restrict__ W1,  const float* __restrict__ b1,
    const float* __restrict__ g1,  const float* __restrict__ be1,
    const float* __restrict__ W2,  const float* __restrict__ b2,
    const float* __restrict__ Wq,  const float* __restrict__ bq,
    const float* __restrict__ Wk,  const float* __restrict__ bk,
    const float* __restrict__ Wv,  const float* __restrict__ bv,
    const float* __restrict__ Wo,  const float* __restrict__ bo,
    const float* __restrict__ Wf1, const float* __restrict__ bf1,
    const float* __restrict__ Wf2, const float* __restrict__ bf2)
{
    int b = blockIdx.x;
    int t = threadIdx.x;
    __shared__ float sk[KMAX][EDIM];
    __shared__ float sv[KMAX][EDIM];

    float ev = eigenvalues[b*KMAX + t];

    float y[EDIM];
    float mean = 0.f;
#pragma unroll
    for (int j = 0; j < EDIM; j++) { y[j] = ev*W1[j] + b1[j]; mean += y[j]; }
    mean *= (1.f/EDIM);
    float var = 0.f;
#pragma unroll
    for (int j = 0; j < EDIM; j++) { float d = y[j]-mean; var += d*d; }
    var *= (1.f/EDIM);
    float rstd = rsqrtf(var + 1e-5f);
#pragma unroll
    for (int j = 0; j < EDIM; j++)
        y[j] = fmaxf((y[j]-mean)*rstd*g1[j] + be1[j], 0.f);

    float h[EDIM];
#pragma unroll
    for (int j = 0; j < EDIM; j++) {
        float s = b2[j];
#pragma unroll
        for (int i = 0; i < EDIM; i++) s += y[i]*W2[i*EDIM+j];
        h[j] = s;
    }

    float q[EDIM];
#pragma unroll
    for (int j = 0; j < EDIM; j++) {
        float sq = bq[j], skk = bk[j], svv = bv[j];
#pragma unroll
        for (int i = 0; i < EDIM; i++) {
            sq  += h[i]*Wq[i*EDIM+j];
            skk += h[i]*Wk[i*EDIM+j];
            svv += h[i]*Wv[i*EDIM+j];
        }
        q[j] = sq; sk[t][j] = skk; sv[t][j] = svv;
    }
    __syncthreads();

    float ctx[EDIM];
#pragma unroll
    for (int hd = 0; hd < 2; hd++) {
        float sc[KMAX];
        float mx = -3.0e38f;
        for (int s = 0; s < KMAX; s++) {
            float d = 0.f;
#pragma unroll
            for (int dd = 0; dd < 8; dd++) d += q[hd*8+dd]*sk[s][hd*8+dd];
            d *= 0.3535533905932738f;
            sc[s] = d;
            mx = fmaxf(mx, d);
        }
        float den = 0.f;
        float cacc[8] = {0,0,0,0,0,0,0,0};
        for (int s = 0; s < KMAX; s++) {
            float w = expf(sc[s]-mx);
            den += w;
#pragma unroll
            for (int dd = 0; dd < 8; dd++) cacc[dd] += w*sv[s][hd*8+dd];
        }
        float inv = 1.f/den;
#pragma unroll
        for (int dd = 0; dd < 8; dd++) ctx[hd*8+dd] = cacc[dd]*inv;
    }

    float co[EDIM];
#pragma unroll
    for (int j = 0; j < EDIM; j++) {
        float s = bo[j];
#pragma unroll
        for (int i = 0; i < EDIM; i++) s += ctx[i]*Wo[i*EDIM+j];
        co[j] = s;
    }

    float fo[32];
#pragma unroll
    for (int o = 0; o < 32; o++) {
        float s = bf1[o];
#pragma unroll
        for (int i = 0; i < EDIM; i++) s += co[i]*Wf1[i*32+o];
        fo[o] = fmaxf(s, 0.f);
    }
    float val = bf2[0];
#pragma unroll
    for (int o = 0; o < 32; o++) val += fo[o]*Wf2[o];
    g_filt[b*KMAX + t] = tanhf(val);
}

// ===========================================================================
// Kernel B (mma.sync bf16-split): x_freq partials via tensor cores.
// Direct load->convert (no register prefetch) at 3 CTAs/SM: trade registers
// for warps — 24 warps/SM hide LDG/LDSM/mma latency that 16 could not.
// ===========================================================================
#define XF_VH   0
#define XF_VL   (XF_VH + 64*144)
#define XF_XH   (XF_VL + 64*144)
#define XF_XL   (XF_XH + 64*272)
#define XF_SMEM (XF_XL + 64*272)      // 53248 B

__global__ void __launch_bounds__(256, 3) xfreq_mma_kernel(
    const float* __restrict__ X, const float* __restrict__ V)
{
    extern __shared__ __align__(16) char smem[];
    uint32_t sb = (uint32_t)__cvta_generic_to_shared(smem);
    int tid = threadIdx.x, wid = tid >> 5, lane = tid & 31;
    int dt = blockIdx.x, seg = blockIdx.y, b = blockIdx.z;

    const float* Vb = V + ((size_t)b*NPG + (size_t)seg*SEGN)*KMAX;
    const float* Xb = X + ((size_t)b*NPG + (size_t)seg*SEGN)*DIN + dt*128;

    int m0    = (wid & 1)*32;
    int ncol0 = (wid >> 1)*32;
    int l7 = lane & 7, g1b = (lane >> 3) & 1, g2b = (lane >> 4) & 1;

    // per-thread load coordinates
    int rV = tid >> 4, cV = tid & 15;   // V: rows rV + it*16, col cV*4
    int rX = tid >> 5, cX = tid & 31;   // X: rows rX + it*8,  col cX*4

    float acc[2][4][4];
#pragma unroll
    for (int mt = 0; mt < 2; mt++)
#pragma unroll
        for (int j = 0; j < 4; j++)
#pragma unroll
            for (int c = 0; c < 4; c++) acc[mt][j][c] = 0.f;

    for (int n0 = 0; n0 < SEGN; n0 += 64) {
        __syncthreads();
        // direct global load -> split -> smem (no long-lived registers)
#pragma unroll
        for (int it = 0; it < 4; it++) {
            float4 v = *(const float4*)&Vb[(size_t)(n0 + rV + it*16)*KMAX + cV*4];
            split_store(smem + XF_VH, smem + XF_VL,
                        (uint32_t)((rV + it*16)*144 + cV*8), v);
        }
#pragma unroll
        for (int it = 0; it < 8; it++) {
            float4 v = *(const float4*)&Xb[(size_t)(n0 + rX + it*8)*DIN + cX*4];
            split_store(smem + XF_XH, smem + XF_XL,
                        (uint32_t)((rX + it*8)*272 + cX*8), v);
        }
        __syncthreads();

#pragma unroll
        for (int ks = 0; ks < 4; ks++) {
            uint32_t ah[2][4], al[2][4];
#pragma unroll
            for (int mt = 0; mt < 2; mt++) {
                uint32_t off = (uint32_t)((ks*16 + g2b*8 + l7)*144
                                          + (m0 + mt*16 + g1b*8)*2);
                ldmx4t(ah[mt], sb + XF_VH + off);
                ldmx4t(al[mt], sb + XF_VL + off);
            }
#pragma unroll
            for (int ng = 0; ng < 2; ng++) {
                uint32_t off = (uint32_t)((ks*16 + g1b*8 + l7)*272
                                          + (ncol0 + ng*16 + g2b*8)*2);
                uint32_t bh[4], bl[4];
                ldmx4t(bh, sb + XF_XH + off);
                ldmx4t(bl, sb + XF_XL + off);
#pragma unroll
                for (int mt = 0; mt < 2; mt++) {
                    mma_bf16(acc[mt][ng*2+0], ah[mt], bh[0], bh[1]);
                    mma_bf16(acc[mt][ng*2+1], ah[mt], bh[2], bh[3]);
                    mma_bf16(acc[mt][ng*2+0], ah[mt], bl[0], bl[1]);
                    mma_bf16(acc[mt][ng*2+1], ah[mt], bl[2], bl[3]);
                    mma_bf16(acc[mt][ng*2+0], al[mt], bh[0], bh[1]);
                    mma_bf16(acc[mt][ng*2+1], al[mt], bh[2], bh[3]);
                }
            }
        }
    }

    float* outp = g_part + ((size_t)seg*BATCH + b)*KMAX*DIN;
#pragma unroll
    for (int mt = 0; mt < 2; mt++) {
        int rk = m0 + mt*16 + (lane >> 2);
#pragma unroll
        for (int j = 0; j < 4; j++) {
            int cd = dt*128 + ncol0 + j*8 + (lane & 3)*2;
            *(float2*)&outp[(size_t)rk*DIN + cd] =
                make_float2(acc[mt][j][0], acc[mt][j][1]);
            *(float2*)&outp[(size_t)(rk+8)*DIN + cd] =
                make_float2(acc[mt][j][2], acc[mt][j][3]);
        }
    }
}

// ===========================================================================
// Kernel C: Z = f .* (xfreq @ Wp); emit packed h/l B-fragments (uint4).
// ===========================================================================
__global__ void __launch_bounds__(256) zproj_kernel(const float* __restrict__ Wp)
{
    int b  = blockIdx.x;
    int ct = blockIdx.y;
    __shared__ __align__(16) float As[64][36];
    __shared__ __align__(16) float Bs[32][64];
    __shared__ __align__(16) float Zs[64][65];
    int tid = threadIdx.x, tx = tid & 15, ty = tid >> 4;
    int r0 = b*64, c0 = ct*64;

    float acc[4][4];
#pragma unroll
    for (int i = 0; i < 4; i++)
#pragma unroll
        for (int j = 0; j < 4; j++) acc[i][j] = 0.f;

    const size_t segstride = (size_t)BATCH*KMAX*DIN;

    for (int k0 = 0; k0 < DIN; k0 += 32) {
        __syncthreads();
#pragma unroll
        for (int it = 0; it < 2; it++) {
            int idx = tid + it*256;
            int rr = idx >> 3, jj = idx & 7;
            size_t off = (size_t)(r0+rr)*DIN + k0 + jj*4;
            float4 a  = *(const float4*)&g_part[off];
            float4 a1 = *(const float4*)&g_part[off +   segstride];
            float4 a2 = *(const float4*)&g_part[off + 2*segstride];
            float4 a3 = *(const float4*)&g_part[off + 3*segstride];
            a.x += a1.x + a2.x + a3.x;
            a.y += a1.y + a2.y + a3.y;
            a.z += a1.z + a2.z + a3.z;
            a.w += a1.w + a2.w + a3.w;
            *(float4*)&As[rr][jj*4] = a;
            int kk = idx >> 4, j2 = idx & 15;
            *(float4*)&Bs[kk][j2*4] = *(const float4*)&Wp[(size_t)(k0+kk)*DOUT + c0 + j2*4];
        }
        __syncthreads();
#pragma unroll
        for (int kk = 0; kk < 32; kk++) {
            float a0 = As[ty*4+0][kk];
            float a1 = As[ty*4+1][kk];
            float a2 = As[ty*4+2][kk];
            float a3 = As[ty*4+3][kk];
            float4 bb = *(const float4*)&Bs[kk][tx*4];
            float ba[4] = {bb.x, bb.y, bb.z, bb.w};
#pragma unroll
            for (int j = 0; j < 4; j++) {
                acc[0][j] += a0*ba[j];
                acc[1][j] += a1*ba[j];
                acc[2][j] += a2*ba[j];
                acc[3][j] += a3*ba[j];
            }
        }
    }

#pragma unroll
    for (int i = 0; i < 4; i++) {
        int k = ty*4 + i;
        float f = g_filt[r0 + k];
#pragma unroll
        for (int j = 0; j < 4; j++)
            Zs[k][tx*4 + j] = acc[i][j]*f;
    }
    __syncthreads();

#pragma unroll
    for (int it = 0; it < 4; it++) {
        int slot = tid + it*256;
        int lane = slot & 31, ks = (slot >> 5) & 3, n8l = slot >> 7;
        int nl = n8l*8 + (lane >> 2);
        int k  = ks*16 + (lane & 3)*2;
        float z0 = Zs[k    ][nl], z1 = Zs[k+1][nl];
        float z2 = Zs[k+8  ][nl], z3 = Zs[k+9][nl];
        uint32_t u0 = __float_as_uint(z0), u1 = __float_as_uint(z1);
        uint32_t u2 = __float_as_uint(z2), u3 = __float_as_uint(z3);
        uint32_t h01 = __byte_perm(u0, u1, 0x7632);
        uint32_t h23 = __byte_perm(u2, u3, 0x7632);
        float l0 = z0 + __uint_as_float((u0 & 0xFFFF0000u) ^ 0x80000000u);
        float l1 = z1 + __uint_as_float((u1 & 0xFFFF0000u) ^ 0x80000000u);
        float l2 = z2 + __uint_as_float((u2 & 0xFFFF0000u) ^ 0x80000000u);
        float l3 = z3 + __uint_as_float((u3 & 0xFFFF0000u) ^ 0x80000000u);
        uint32_t lo01 = __byte_perm(__float_as_uint(l0), __float_as_uint(l1), 0x7632);
        uint32_t lo23 = __byte_perm(__float_as_uint(l2), __float_as_uint(l3), 0x7632);
        size_t fi = ((size_t)(b*32 + ct*8 + n8l)*4 + ks)*32 + lane;
        g_Zfrag[fi] = make_uint4(h01, h23, lo01, lo23);
    }
}

// ===========================================================================
// Kernel D (mma.sync bf16-split): out = LN( V_b @ Z_b^T + bp ).
// B fragments via single LDG.128 (h+l packed, direct from L2). A-only smem,
// 3 CTAs/SM. (R10 config — measured best for D; cp.async staging regressed.)
// ===========================================================================
#define D_BP    0
#define D_GP    1024
#define D_BEP   2048
#define D_PART  3072
#define D_STATS 5120
#define D_AH    5632
#define D_AL    (D_AH + 32*144)
#define SMEM_D  (D_AL + 32*144)       // 14848 B

__global__ void __launch_bounds__(256, 3) out_mma_kernel(
    const float* __restrict__ V,
    const float* __restrict__ bp, const float* __restrict__ gp,
    const float* __restrict__ bep, float* __restrict__ out)
{
    extern __shared__ __align__(16) char smem[];
    uint32_t sb = (uint32_t)__cvta_generic_to_shared(smem);
    int tid = threadIdx.x, wid = tid >> 5, lane = tid & 31;
    int rc = blockIdx.x, b = blockIdx.y;

    float* s_bp  = (float*)(smem + D_BP);
    float* s_gp  = (float*)(smem + D_GP);
    float* s_bep = (float*)(smem + D_BEP);
    s_bp[tid]  = bp[tid];
    s_gp[tid]  = gp[tid];
    s_bep[tid] = bep[tid];

    const float* Vb = V + ((size_t)b*NPG + (size_t)rc*32)*KMAX;
#pragma unroll
    for (int it = 0; it < 2; it++) {
        int idx = tid + it*256;
        int r = idx >> 4, jj = idx & 15;
        float4 v = *(const float4*)&Vb[(size_t)r*KMAX + jj*4];
        split_store(smem + D_AH, smem + D_AL, (uint32_t)(r*144 + jj*8), v);
    }
    __syncthreads();

    int ncol0 = wid*32;
    int aRow = (lane & 7) + ((lane >> 3) & 1)*8;
    int aCol = (lane >> 4)*8;

    float acc[2][4][4];
#pragma unroll
    for (int mt = 0; mt < 2; mt++)
#pragma unroll
        for (int nt = 0; nt < 4; nt++)
#pragma unroll
            for (int j = 0; j < 4; j++) acc[mt][nt][j] = 0.f;

    const uint4* Z = g_Zfrag + ((size_t)b*32 + wid*4)*4*32;

#pragma unroll
    for (int ks = 0; ks < 4; ks++) {
        uint4 bz[4];
#pragma unroll
        for (int n8 = 0; n8 < 4; n8++)
            bz[n8] = Z[((size_t)n8*4 + ks)*32 + lane];
        uint32_t ah[2][4], al[2][4];
#pragma unroll
        for (int mt = 0; mt < 2; mt++) {
            uint32_t off = (uint32_t)((mt*16 + aRow)*144 + (ks*16 + aCol)*2);
            ldmx4(ah[mt], sb + D_AH + off);
            ldmx4(al[mt], sb + D_AL + off);
        }
#pragma unroll
        for (int n8 = 0; n8 < 4; n8++)
#pragma unroll
            for (int mt = 0; mt < 2; mt++) {
                mma_bf16(acc[mt][n8], ah[mt], bz[n8].x, bz[n8].y);
                mma_bf16(acc[mt][n8], ah[mt], bz[n8].z, bz[n8].w);
                mma_bf16(acc[mt][n8], al[mt], bz[n8].x, bz[n8].y);
            }
    }

#pragma unroll
    for (int mt = 0; mt < 2; mt++)
#pragma unroll
        for (int n8 = 0; n8 < 4; n8++) {
            int c0 = ncol0 + n8*8 + (lane & 3)*2;
            acc[mt][n8][0] += s_bp[c0];
            acc[mt][n8][1] += s_bp[c0+1];
            acc[mt][n8][2] += s_bp[c0];
            acc[mt][n8][3] += s_bp[c0+1];
        }

    float rs[4], rq[4];
#pragma unroll
    for (int mt = 0; mt < 2; mt++) {
        float s0=0.f,q0=0.f,s1=0.f,q1=0.f;
#pragma unroll
        for (int n8 = 0; n8 < 4; n8++) {
            s0 += acc[mt][n8][0] + acc[mt][n8][1];
            q0 += acc[mt][n8][0]*acc[mt][n8][0] + acc[mt][n8][1]*acc[mt][n8][1];
            s1 += acc[mt][n8][2] + acc[mt][n8][3];
            q1 += acc[mt][n8][2]*acc[mt][n8][2] + acc[mt][n8][3]*acc[mt][n8][3];
        }
        rs[mt*2+0]=s0; rq[mt*2+0]=q0; rs[mt*2+1]=s1; rq[mt*2+1]=q1;
    }
#pragma unroll
    for (int i = 0; i < 4; i++) {
        rs[i] += __shfl_xor_sync(0xffffffffu, rs[i], 1);
        rs[i] += __shfl_xor_sync(0xffffffffu, rs[i], 2);
        rq[i] += __shfl_xor_sync(0xffffffffu, rq[i], 1);
        rq[i] += __shfl_xor_sync(0xffffffffu, rq[i], 2);
    }
    float2* part = (float2*)(smem + D_PART);
    if ((lane & 3) == 0) {
#pragma unroll
        for (int i = 0; i < 4; i++) {
            int row = (i >> 1)*16 + (i & 1)*8 + (lane >> 2);
            part[row*8 + wid] = make_float2(rs[i], rq[i]);
        }
    }
    __syncthreads();

    float2* stats = (float2*)(smem + D_STATS);
    if (tid < 32) {
        float s = 0.f, q = 0.f;
#pragma unroll
        for (int w = 0; w < 8; w++) {
            float2 p = part[tid*8 + w];
            s += p.x; q += p.y;
        }
        float mean = s*(1.f/256.f);
        float var = q*(1.f/256.f) - mean*mean;
        stats[tid] = make_float2(mean, rsqrtf(var + 1e-5f));
    }
    __syncthreads();

    size_t m0 = (size_t)b*NPG + (size_t)rc*32;
#pragma unroll
    for (int mt = 0; mt < 2; mt++)
#pragma unroll
        for (int half = 0; half < 2; half++) {
            int row = mt*16 + half*8 + (lane >> 2);
            float2 mr = stats[row];
#pragma unroll
            for (int n8 = 0; n8 < 4; n8++) {
                int c0 = ncol0 + n8*8 + (lane & 3)*2;
                float v0 = acc[mt][n8][half*2+0];
                float v1 = acc[mt][n8][half*2+1];
                float2 o2;
                o2.x = (v0 - mr.x)*mr.y*s_gp[c0]   + s_bep[c0];
                o2.y = (v1 - mr.x)*mr.y*s_gp[c0+1] + s_bep[c0+1];
                *(float2*)&out[(m0 + row)*DOUT + c0] = o2;
            }
        }
}

// ---------------------------------------------------------------------------
extern "C" void kernel_launch(void* const* d_in, const int* in_sizes, int n_in,
                              void* d_out, int out_size)
{
    const float* x    = (const float*)d_in[0];
    const float* evec = (const float*)d_in[1];
    const float* eval = (const float*)d_in[2];
    int wb = n_in - 22;
    const float* W1  = (const float*)d_in[wb + 0];
    const float* b1  = (const float*)d_in[wb + 1];
    const float* g1  = (const float*)d_in[wb + 2];
    const float* be1 = (const float*)d_in[wb + 3];
    const float* W2  = (const float*)d_in[wb + 4];
    const float* b2  = (const float*)d_in[wb + 5];
    const float* Wq  = (const float*)d_in[wb + 6];
    const float* bq  = (const float*)d_in[wb + 7];
    const float* Wk  = (const float*)d_in[wb + 8];
    const float* bk  = (const float*)d_in[wb + 9];
    const float* Wv  = (const float*)d_in[wb + 10];
    const float* bv  = (const float*)d_in[wb + 11];
    const float* Wo  = (const float*)d_in[wb + 12];
    const float* bo  = (const float*)d_in[wb + 13];
    const float* Wf1 = (const float*)d_in[wb + 14];
    const float* bf1 = (const float*)d_in[wb + 15];
    const float* Wf2 = (const float*)d_in[wb + 16];
    const float* bf2 = (const float*)d_in[wb + 17];
    const float* Wp  = (const float*)d_in[wb + 18];
    const float* bp  = (const float*)d_in[wb + 19];
    const float* gp  = (const float*)d_in[wb + 20];
    const float* bep = (const float*)d_in[wb + 21];
    float* out = (float*)d_out;

    cudaFuncSetAttribute(xfreq_mma_kernel,
                         cudaFuncAttributeMaxDynamicSharedMemorySize, XF_SMEM);
    cudaFuncSetAttribute(out_mma_kernel,
                         cudaFuncAttributeMaxDynamicSharedMemorySize, SMEM_D);

    filter_kernel<<<BATCH, KMAX>>>(eval,
        W1, b1, g1, be1, W2, b2, Wq, bq, Wk, bk, Wv, bv, Wo, bo,
        Wf1, bf1, Wf2, bf2);
    xfreq_mma_kernel<<<dim3(DIN/128, NSEG, BATCH), 256, XF_SMEM>>>(x, evec);
    zproj_kernel<<<dim3(BATCH, 4), 256>>>(Wp);
    out_mma_kernel<<<dim3(NPG/32, BATCH), 256, SMEM_D>>>(evec, bp, gp, bep, out);
}

// round 15
// speedup vs baseline: 1.0998x; 1.0998x over previous
#include <cuda_runtime.h>
#include <cuda_bf16.h>
#include <math.h>
#include <stdint.h>

#define BATCH 64
#define NPG   2048
#define KMAX  64
#define DIN   256
#define DOUT  256
#define EDIM  16
#define NSEG  4
#define SEGN  (NPG/NSEG)

// Scratch (no allocations allowed)
__device__ float g_filt[BATCH*KMAX];                       // 16 KB
__device__ float g_part[(size_t)NSEG*BATCH*KMAX*DIN];      // 16 MB partial x_freq
// Z in mma-B-fragment order, h+l packed: [b][n8(32)][ks(4)][lane(32)] uint4
__device__ uint4 g_Zfrag[(size_t)BATCH*32*4*32];           // 4 MB

// ===========================================================================
// mma.sync helpers (portable tensor-core path; tcgen05 rejected by the
// harness's compute_103 virtual arch)
// ===========================================================================
__device__ __forceinline__ void ldmx4(uint32_t* r, uint32_t addr) {
    asm volatile("ldmatrix.sync.aligned.m8n8.x4.shared.b16 {%0,%1,%2,%3}, [%4];"
                 : "=r"(r[0]), "=r"(r[1]), "=r"(r[2]), "=r"(r[3]) : "r"(addr));
}
__device__ __forceinline__ void ldmx4t(uint32_t* r, uint32_t addr) {
    asm volatile("ldmatrix.sync.aligned.m8n8.x4.trans.shared.b16 {%0,%1,%2,%3}, [%4];"
                 : "=r"(r[0]), "=r"(r[1]), "=r"(r[2]), "=r"(r[3]) : "r"(addr));
}

__device__ __forceinline__ void mma_bf16(float* d, const uint32_t* a,
                                         uint32_t b0, uint32_t b1) {
    asm volatile(
        "mma.sync.aligned.m16n8k16.row.col.f32.bf16.bf16.f32 "
        "{%0,%1,%2,%3}, {%4,%5,%6,%7}, {%8,%9}, {%0,%1,%2,%3};"
        : "+f"(d[0]), "+f"(d[1]), "+f"(d[2]), "+f"(d[3])
        : "r"(a[0]), "r"(a[1]), "r"(a[2]), "r"(a[3]), "r"(b0), "r"(b1));
}

// Truncation-based hi/lo split: hi = top 16 bits (PRMT pack), lo = x - hi.
__device__ __forceinline__ void split_store(char* base_h, char* base_l,
                                            uint32_t off, float4 v) {
    uint32_t u0 = __float_as_uint(v.x), u1 = __float_as_uint(v.y);
    uint32_t u2 = __float_as_uint(v.z), u3 = __float_as_uint(v.w);
    uint32_t h01 = __byte_perm(u0, u1, 0x7632);
    uint32_t h23 = __byte_perm(u2, u3, 0x7632);
    float l0 = v.x + __uint_as_float((u0 & 0xFFFF0000u) ^ 0x80000000u);
    float l1 = v.y + __uint_as_float((u1 & 0xFFFF0000u) ^ 0x80000000u);
    float l2 = v.z + __uint_as_float((u2 & 0xFFFF0000u) ^ 0x80000000u);
    float l3 = v.w + __uint_as_float((u3 & 0xFFFF0000u) ^ 0x80000000u);
    uint32_t lo01 = __byte_perm(__float_as_uint(l0), __float_as_uint(l1), 0x7632);
    uint32_t lo23 = __byte_perm(__float_as_uint(l2), __float_as_uint(l3), 0x7632);
    *(uint2*)(base_h + off) = make_uint2(h01, h23);
    *(uint2*)(base_l + off) = make_uint2(lo01, lo23);
}

// ===========================================================================
// Kernel A: per-batch eigenvalue encoder + attention + filter MLP (tiny)
// ===========================================================================
__global__ void filter_kernel(
    const float* __restrict__ eigenvalues,
    const float* __restrict__ W1,  const float* __restrict__ b1,
    const float* __restrict__ g1,  const float* __restrict__ be1,
    const float* __restrict__ W2,  const float* __restrict__ b2,
    const float* __restrict__ Wq,  const float* __restrict__ bq,
    const float* __restrict__ Wk,  const float* __restrict__ bk,
    const float* __restrict__ Wv,  const float* __restrict__ bv,
    const float* __restrict__ Wo,  const float* __restrict__ bo,
    const float* __restrict__ Wf1, const float* __restrict__ bf1,
    const float* __restrict__ Wf2, const float* __restrict__ bf2)
{
    int b = blockIdx.x;
    int t = threadIdx.x;
    __shared__ float sk[KMAX][EDIM];
    __shared__ float sv[KMAX][EDIM];

    float ev = eigenvalues[b*KMAX + t];

    float y[EDIM];
    float mean = 0.f;
#pragma unroll
    for (int j = 0; j < EDIM; j++) { y[j] = ev*W1[j] + b1[j]; mean += y[j]; }
    mean *= (1.f/EDIM);
    float var = 0.f;
#pragma unroll
    for (int j = 0; j < EDIM; j++) { float d = y[j]-mean; var += d*d; }
    var *= (1.f/EDIM);
    float rstd = rsqrtf(var + 1e-5f);
#pragma unroll
    for (int j = 0; j < EDIM; j++)
        y[j] = fmaxf((y[j]-mean)*rstd*g1[j] + be1[j], 0.f);

    float h[EDIM];
#pragma unroll
    for (int j = 0; j < EDIM; j++) {
        float s = b2[j];
#pragma unroll
        for (int i = 0; i < EDIM; i++) s += y[i]*W2[i*EDIM+j];
        h[j] = s;
    }

    float q[EDIM];
#pragma unroll
    for (int j = 0; j < EDIM; j++) {
        float sq = bq[j], skk = bk[j], svv = bv[j];
#pragma unroll
        for (int i = 0; i < EDIM; i++) {
            sq  += h[i]*Wq[i*EDIM+j];
            skk += h[i]*Wk[i*EDIM+j];
            svv += h[i]*Wv[i*EDIM+j];
        }
        q[j] = sq; sk[t][j] = skk; sv[t][j] = svv;
    }
    __syncthreads();

    float ctx[EDIM];
#pragma unroll
    for (int hd = 0; hd < 2; hd++) {
        float sc[KMAX];
        float mx = -3.0e38f;
        for (int s = 0; s < KMAX; s++) {
            float d = 0.f;
#pragma unroll
            for (int dd = 0; dd < 8; dd++) d += q[hd*8+dd]*sk[s][hd*8+dd];
            d *= 0.3535533905932738f;
            sc[s] = d;
            mx = fmaxf(mx, d);
        }
        float den = 0.f;
        float cacc[8] = {0,0,0,0,0,0,0,0};
        for (int s = 0; s < KMAX; s++) {
            float w = expf(sc[s]-mx);
            den += w;
#pragma unroll
            for (int dd = 0; dd < 8; dd++) cacc[dd] += w*sv[s][hd*8+dd];
        }
        float inv = 1.f/den;
#pragma unroll
        for (int dd = 0; dd < 8; dd++) ctx[hd*8+dd] = cacc[dd]*inv;
    }

    float co[EDIM];
#pragma unroll
    for (int j = 0; j < EDIM; j++) {
        float s = bo[j];
#pragma unroll
        for (int i = 0; i < EDIM; i++) s += ctx[i]*Wo[i*EDIM+j];
        co[j] = s;
    }

    float fo[32];
#pragma unroll
    for (int o = 0; o < 32; o++) {
        float s = bf1[o];
#pragma unroll
        for (int i = 0; i < EDIM; i++) s += co[i]*Wf1[i*32+o];
        fo[o] = fmaxf(s, 0.f);
    }
    float val = bf2[0];
#pragma unroll
    for (int o = 0; o < 32; o++) val += fo[o]*Wf2[o];
    g_filt[b*KMAX + t] = tanhf(val);
}

// ===========================================================================
// Kernel B (mma.sync bf16-split): x_freq partials via tensor cores.
// Single-buffer + register prefetch (measured best across R6-R13 variants):
// iteration = [convert regs -> smem] sync [LDG prefetch i+1] [mma] sync.
// ===========================================================================
#define XF_VH   0
#define XF_VL   (XF_VH + 64*144)
#define XF_XH   (XF_VL + 64*144)
#define XF_XL   (XF_XH + 64*272)
#define XF_SMEM (XF_XL + 64*272)      // 53248 B

__global__ void __launch_bounds__(256, 2) xfreq_mma_kernel(
    const float* __restrict__ X, const float* __restrict__ V)
{
    extern __shared__ __align__(16) char smem[];
    uint32_t sb = (uint32_t)__cvta_generic_to_shared(smem);
    int tid = threadIdx.x, wid = tid >> 5, lane = tid & 31;
    int dt = blockIdx.x, seg = blockIdx.y, b = blockIdx.z;

    const float* Vb = V + ((size_t)b*NPG + (size_t)seg*SEGN)*KMAX;
    const float* Xb = X + ((size_t)b*NPG + (size_t)seg*SEGN)*DIN + dt*128;

    int m0    = (wid & 1)*32;
    int ncol0 = (wid >> 1)*32;
    int l7 = lane & 7, g1b = (lane >> 3) & 1, g2b = (lane >> 4) & 1;

    // per-thread load coordinates
    int rV = tid >> 4, cV = tid & 15;   // V: rows rV + it*16, col cV*4
    int rX = tid >> 5, cX = tid & 31;   // X: rows rX + it*8,  col cX*4

    float acc[2][4][4];
#pragma unroll
    for (int mt = 0; mt < 2; mt++)
#pragma unroll
        for (int j = 0; j < 4; j++)
#pragma unroll
            for (int c = 0; c < 4; c++) acc[mt][j][c] = 0.f;

    float4 vreg[4], xreg[8];
    // preload chunk 0
#pragma unroll
    for (int it = 0; it < 4; it++)
        vreg[it] = *(const float4*)&Vb[(size_t)(rV + it*16)*KMAX + cV*4];
#pragma unroll
    for (int it = 0; it < 8; it++)
        xreg[it] = *(const float4*)&Xb[(size_t)(rX + it*8)*DIN + cX*4];

    for (int n0 = 0; n0 < SEGN; n0 += 64) {
        // convert registers -> smem (pure ALU+STS, data already resident)
#pragma unroll
        for (int it = 0; it < 4; it++)
            split_store(smem + XF_VH, smem + XF_VL,
                        (uint32_t)((rV + it*16)*144 + cV*8), vreg[it]);
#pragma unroll
        for (int it = 0; it < 8; it++)
            split_store(smem + XF_XH, smem + XF_XL,
                        (uint32_t)((rX + it*8)*272 + cX*8), xreg[it]);
        __syncthreads();

        // prefetch next chunk (LDGs retire during the mma phase below)
        if (n0 + 64 < SEGN) {
            const float* Vn = Vb + (size_t)(n0 + 64)*KMAX;
            const float* Xn = Xb + (size_t)(n0 + 64)*DIN;
#pragma unroll
            for (int it = 0; it < 4; it++)
                vreg[it] = *(const float4*)&Vn[(size_t)(rV + it*16)*KMAX + cV*4];
#pragma unroll
            for (int it = 0; it < 8; it++)
                xreg[it] = *(const float4*)&Xn[(size_t)(rX + it*8)*DIN + cX*4];
        }

#pragma unroll
        for (int ks = 0; ks < 4; ks++) {
            uint32_t ah[2][4], al[2][4];
#pragma unroll
            for (int mt = 0; mt < 2; mt++) {
                uint32_t off = (uint32_t)((ks*16 + g2b*8 + l7)*144
                                          + (m0 + mt*16 + g1b*8)*2);
                ldmx4t(ah[mt], sb + XF_VH + off);
                ldmx4t(al[mt], sb + XF_VL + off);
            }
#pragma unroll
            for (int ng = 0; ng < 2; ng++) {
                uint32_t off = (uint32_t)((ks*16 + g1b*8 + l7)*272
                                          + (ncol0 + ng*16 + g2b*8)*2);
                uint32_t bh[4], bl[4];
                ldmx4t(bh, sb + XF_XH + off);
                ldmx4t(bl, sb + XF_XL + off);
#pragma unroll
                for (int mt = 0; mt < 2; mt++) {
                    mma_bf16(acc[mt][ng*2+0], ah[mt], bh[0], bh[1]);
                    mma_bf16(acc[mt][ng*2+1], ah[mt], bh[2], bh[3]);
                    mma_bf16(acc[mt][ng*2+0], ah[mt], bl[0], bl[1]);
                    mma_bf16(acc[mt][ng*2+1], ah[mt], bl[2], bl[3]);
                    mma_bf16(acc[mt][ng*2+0], al[mt], bh[0], bh[1]);
                    mma_bf16(acc[mt][ng*2+1], al[mt], bh[2], bh[3]);
                }
            }
        }
        __syncthreads();
    }

    float* outp = g_part + ((size_t)seg*BATCH + b)*KMAX*DIN;
#pragma unroll
    for (int mt = 0; mt < 2; mt++) {
        int rk = m0 + mt*16 + (lane >> 2);
#pragma unroll
        for (int j = 0; j < 4; j++) {
            int cd = dt*128 + ncol0 + j*8 + (lane & 3)*2;
            *(float2*)&outp[(size_t)rk*DIN + cd] =
                make_float2(acc[mt][j][0], acc[mt][j][1]);
            *(float2*)&outp[(size_t)(rk+8)*DIN + cd] =
                make_float2(acc[mt][j][2], acc[mt][j][3]);
        }
    }
}

// ===========================================================================
// Kernel C: Z = f .* (xfreq @ Wp); emit packed h/l B-fragments (uint4).
// ===========================================================================
__global__ void __launch_bounds__(256) zproj_kernel(const float* __restrict__ Wp)
{
    int b  = blockIdx.x;
    int ct = blockIdx.y;
    __shared__ __align__(16) float As[64][36];
    __shared__ __align__(16) float Bs[32][64];
    __shared__ __align__(16) float Zs[64][65];
    int tid = threadIdx.x, tx = tid & 15, ty = tid >> 4;
    int r0 = b*64, c0 = ct*64;

    float acc[4][4];
#pragma unroll
    for (int i = 0; i < 4; i++)
#pragma unroll
        for (int j = 0; j < 4; j++) acc[i][j] = 0.f;

    const size_t segstride = (size_t)BATCH*KMAX*DIN;

    for (int k0 = 0; k0 < DIN; k0 += 32) {
        __syncthreads();
#pragma unroll
        for (int it = 0; it < 2; it++) {
            int idx = tid + it*256;
            int rr = idx >> 3, jj = idx & 7;
            size_t off = (size_t)(r0+rr)*DIN + k0 + jj*4;
            float4 a  = *(const float4*)&g_part[off];
            float4 a1 = *(const float4*)&g_part[off +   segstride];
            float4 a2 = *(const float4*)&g_part[off + 2*segstride];
            float4 a3 = *(const float4*)&g_part[off + 3*segstride];
            a.x += a1.x + a2.x + a3.x;
            a.y += a1.y + a2.y + a3.y;
            a.z += a1.z + a2.z + a3.z;
            a.w += a1.w + a2.w + a3.w;
            *(float4*)&As[rr][jj*4] = a;
            int kk = idx >> 4, j2 = idx & 15;
            *(float4*)&Bs[kk][j2*4] = *(const float4*)&Wp[(size_t)(k0+kk)*DOUT + c0 + j2*4];
        }
        __syncthreads();
#pragma unroll
        for (int kk = 0; kk < 32; kk++) {
            float a0 = As[ty*4+0][kk];
            float a1 = As[ty*4+1][kk];
            float a2 = As[ty*4+2][kk];
            float a3 = As[ty*4+3][kk];
            float4 bb = *(const float4*)&Bs[kk][tx*4];
            float ba[4] = {bb.x, bb.y, bb.z, bb.w};
#pragma unroll
            for (int j = 0; j < 4; j++) {
                acc[0][j] += a0*ba[j];
                acc[1][j] += a1*ba[j];
                acc[2][j] += a2*ba[j];
                acc[3][j] += a3*ba[j];
            }
        }
    }

#pragma unroll
    for (int i = 0; i < 4; i++) {
        int k = ty*4 + i;
        float f = g_filt[r0 + k];
#pragma unroll
        for (int j = 0; j < 4; j++)
            Zs[k][tx*4 + j] = acc[i][j]*f;
    }
    __syncthreads();

#pragma unroll
    for (int it = 0; it < 4; it++) {
        int slot = tid + it*256;
        int lane = slot & 31, ks = (slot >> 5) & 3, n8l = slot >> 7;
        int nl = n8l*8 + (lane >> 2);
        int k  = ks*16 + (lane & 3)*2;
        float z0 = Zs[k    ][nl], z1 = Zs[k+1][nl];
        float z2 = Zs[k+8  ][nl], z3 = Zs[k+9][nl];
        uint32_t u0 = __float_as_uint(z0), u1 = __float_as_uint(z1);
        uint32_t u2 = __float_as_uint(z2), u3 = __float_as_uint(z3);
        uint32_t h01 = __byte_perm(u0, u1, 0x7632);
        uint32_t h23 = __byte_perm(u2, u3, 0x7632);
        float l0 = z0 + __uint_as_float((u0 & 0xFFFF0000u) ^ 0x80000000u);
        float l1 = z1 + __uint_as_float((u1 & 0xFFFF0000u) ^ 0x80000000u);
        float l2 = z2 + __uint_as_float((u2 & 0xFFFF0000u) ^ 0x80000000u);
        float l3 = z3 + __uint_as_float((u3 & 0xFFFF0000u) ^ 0x80000000u);
        uint32_t lo01 = __byte_perm(__float_as_uint(l0), __float_as_uint(l1), 0x7632);
        uint32_t lo23 = __byte_perm(__float_as_uint(l2), __float_as_uint(l3), 0x7632);
        size_t fi = ((size_t)(b*32 + ct*8 + n8l)*4 + ks)*32 + lane;
        g_Zfrag[fi] = make_uint4(h01, h23, lo01, lo23);
    }
}

// ===========================================================================
// Kernel D (mma.sync bf16-split): out = LN( V_b @ Z_b^T + bp ).
// B fragments via single LDG.128 (h+l packed, direct from L2). A-only smem,
// 3 CTAs/SM. (Measured best for D; cp.async staging regressed.)
// ===========================================================================
#define D_BP    0
#define D_GP    1024
#define D_BEP   2048
#define D_PART  3072
#define D_STATS 5120
#define D_AH    5632
#define D_AL    (D_AH + 32*144)
#define SMEM_D  (D_AL + 32*144)       // 14848 B

__global__ void __launch_bounds__(256, 3) out_mma_kernel(
    const float* __restrict__ V,
    const float* __restrict__ bp, const float* __restrict__ gp,
    const float* __restrict__ bep, float* __restrict__ out)
{
    extern __shared__ __align__(16) char smem[];
    uint32_t sb = (uint32_t)__cvta_generic_to_shared(smem);
    int tid = threadIdx.x, wid = tid >> 5, lane = tid & 31;
    int rc = blockIdx.x, b = blockIdx.y;

    float* s_bp  = (float*)(smem + D_BP);
    float* s_gp  = (float*)(smem + D_GP);
    float* s_bep = (float*)(smem + D_BEP);
    s_bp[tid]  = bp[tid];
    s_gp[tid]  = gp[tid];
    s_bep[tid] = bep[tid];

    const float* Vb = V + ((size_t)b*NPG + (size_t)rc*32)*KMAX;
#pragma unroll
    for (int it = 0; it < 2; it++) {
        int idx = tid + it*256;
        int r = idx >> 4, jj = idx & 15;
        float4 v = *(const float4*)&Vb[(size_t)r*KMAX + jj*4];
        split_store(smem + D_AH, smem + D_AL, (uint32_t)(r*144 + jj*8), v);
    }
    __syncthreads();

    int ncol0 = wid*32;
    int aRow = (lane & 7) + ((lane >> 3) & 1)*8;
    int aCol = (lane >> 4)*8;

    float acc[2][4][4];
#pragma unroll
    for (int mt = 0; mt < 2; mt++)
#pragma unroll
        for (int nt = 0; nt < 4; nt++)
#pragma unroll
            for (int j = 0; j < 4; j++) acc[mt][nt][j] = 0.f;

    const uint4* Z = g_Zfrag + ((size_t)b*32 + wid*4)*4*32;

#pragma unroll
    for (int ks = 0; ks < 4; ks++) {
        uint4 bz[4];
#pragma unroll
        for (int n8 = 0; n8 < 4; n8++)
            bz[n8] = Z[((size_t)n8*4 + ks)*32 + lane];
        uint32_t ah[2][4], al[2][4];
#pragma unroll
        for (int mt = 0; mt < 2; mt++) {
            uint32_t off = (uint32_t)((mt*16 + aRow)*144 + (ks*16 + aCol)*2);
            ldmx4(ah[mt], sb + D_AH + off);
            ldmx4(al[mt], sb + D_AL + off);
        }
#pragma unroll
        for (int n8 = 0; n8 < 4; n8++)
#pragma unroll
            for (int mt = 0; mt < 2; mt++) {
                mma_bf16(acc[mt][n8], ah[mt], bz[n8].x, bz[n8].y);
                mma_bf16(acc[mt][n8], ah[mt], bz[n8].z, bz[n8].w);
                mma_bf16(acc[mt][n8], al[mt], bz[n8].x, bz[n8].y);
            }
    }

#pragma unroll
    for (int mt = 0; mt < 2; mt++)
#pragma unroll
        for (int n8 = 0; n8 < 4; n8++) {
            int c0 = ncol0 + n8*8 + (lane & 3)*2;
            acc[mt][n8][0] += s_bp[c0];
            acc[mt][n8][1] += s_bp[c0+1];
            acc[mt][n8][2] += s_bp[c0];
            acc[mt][n8][3] += s_bp[c0+1];
        }

    float rs[4], rq[4];
#pragma unroll
    for (int mt = 0; mt < 2; mt++) {
        float s0=0.f,q0=0.f,s1=0.f,q1=0.f;
#pragma unroll
        for (int n8 = 0; n8 < 4; n8++) {
            s0 += acc[mt][n8][0] + acc[mt][n8][1];
            q0 += acc[mt][n8][0]*acc[mt][n8][0] + acc[mt][n8][1]*acc[mt][n8][1];
            s1 += acc[mt][n8][2] + acc[mt][n8][3];
            q1 += acc[mt][n8][2]*acc[mt][n8][2] + acc[mt][n8][3]*acc[mt][n8][3];
        }
        rs[mt*2+0]=s0; rq[mt*2+0]=q0; rs[mt*2+1]=s1; rq[mt*2+1]=q1;
    }
#pragma unroll
    for (int i = 0; i < 4; i++) {
        rs[i] += __shfl_xor_sync(0xffffffffu, rs[i], 1);
        rs[i] += __shfl_xor_sync(0xffffffffu, rs[i], 2);
        rq[i] += __shfl_xor_sync(0xffffffffu, rq[i], 1);
        rq[i] += __shfl_xor_sync(0xffffffffu, rq[i], 2);
    }
    float2* part = (float2*)(smem + D_PART);
    if ((lane & 3) == 0) {
#pragma unroll
        for (int i = 0; i < 4; i++) {
            int row = (i >> 1)*16 + (i & 1)*8 + (lane >> 2);
            part[row*8 + wid] = make_float2(rs[i], rq[i]);
        }
    }
    __syncthreads();

    float2* stats = (float2*)(smem + D_STATS);
    if (tid < 32) {
        float s = 0.f, q = 0.f;
#pragma unroll
        for (int w = 0; w < 8; w++) {
            float2 p = part[tid*8 + w];
            s += p.x; q += p.y;
        }
        float mean = s*(1.f/256.f);
        float var = q*(1.f/256.f) - mean*mean;
        stats[tid] = make_float2(mean, rsqrtf(var + 1e-5f));
    }
    __syncthreads();

    size_t m0 = (size_t)b*NPG + (size_t)rc*32;
#pragma unroll
    for (int mt = 0; mt < 2; mt++)
#pragma unroll
        for (int half = 0; half < 2; half++) {
            int row = mt*16 + half*8 + (lane >> 2);
            float2 mr = stats[row];
#pragma unroll
            for (int n8 = 0; n8 < 4; n8++) {
                int c0 = ncol0 + n8*8 + (lane & 3)*2;
                float v0 = acc[mt][n8][half*2+0];
                float v1 = acc[mt][n8][half*2+1];
                float2 o2;
                o2.x = (v0 - mr.x)*mr.y*s_gp[c0]   + s_bep[c0];
                o2.y = (v1 - mr.x)*mr.y*s_gp[c0+1] + s_bep[c0+1];
                *(float2*)&out[(m0 + row)*DOUT + c0] = o2;
            }
        }
}

// ---------------------------------------------------------------------------
extern "C" void kernel_launch(void* const* d_in, const int* in_sizes, int n_in,
                              void* d_out, int out_size)
{
    const float* x    = (const float*)d_in[0];
    const float* evec = (const float*)d_in[1];
    const float* eval = (const float*)d_in[2];
    int wb = n_in - 22;
    const float* W1  = (const float*)d_in[wb + 0];
    const float* b1  = (const float*)d_in[wb + 1];
    const float* g1  = (const float*)d_in[wb + 2];
    const float* be1 = (const float*)d_in[wb + 3];
    const float* W2  = (const float*)d_in[wb + 4];
    const float* b2  = (const float*)d_in[wb + 5];
    const float* Wq  = (const float*)d_in[wb + 6];
    const float* bq  = (const float*)d_in[wb + 7];
    const float* Wk  = (const float*)d_in[wb + 8];
    const float* bk  = (const float*)d_in[wb + 9];
    const float* Wv  = (const float*)d_in[wb + 10];
    const float* bv  = (const float*)d_in[wb + 11];
    const float* Wo  = (const float*)d_in[wb + 12];
    const float* bo  = (const float*)d_in[wb + 13];
    const float* Wf1 = (const float*)d_in[wb + 14];
    const float* bf1 = (const float*)d_in[wb + 15];
    const float* Wf2 = (const float*)d_in[wb + 16];
    const float* bf2 = (const float*)d_in[wb + 17];
    const float* Wp  = (const float*)d_in[wb + 18];
    const float* bp  = (const float*)d_in[wb + 19];
    const float* gp  = (const float*)d_in[wb + 20];
    const float* bep = (const float*)d_in[wb + 21];
    float* out = (float*)d_out;

    cudaFuncSetAttribute(xfreq_mma_kernel,
                         cudaFuncAttributeMaxDynamicSharedMemorySize, XF_SMEM);
    cudaFuncSetAttribute(out_mma_kernel,
                         cudaFuncAttributeMaxDynamicSharedMemorySize, SMEM_D);

    filter_kernel<<<BATCH, KMAX>>>(eval,
        W1, b1, g1, be1, W2, b2, Wq, bq, Wk, bk, Wv, bv, Wo, bo,
        Wf1, bf1, Wf2, bf2);
    xfreq_mma_kernel<<<dim3(DIN/128, NSEG, BATCH), 256, XF_SMEM>>>(x, evec);
    zproj_kernel<<<dim3(BATCH, 4), 256>>>(Wp);
    out_mma_kernel<<<dim3(NPG/32, BATCH), 256, SMEM_D>>>(evec, bp, gp, bep, out);
}